// round 9
// baseline (speedup 1.0000x reference)
#include <cuda_runtime.h>
#include <climits>

// Problem constants (fixed by reference setup_inputs)
#define BB   4096
#define HH   64
#define WW   64
#define HWC  4096          // H*W
#define LATENT 128
#define NT   256           // threads per block
#define CPT  (HWC / NT)    // 16 cells per thread
#define GRID 1216          // 152 SMs * 8 CTAs/SM: one persistent wave

__global__ __launch_bounds__(NT)
void oracle_kernel(const float4* __restrict__ x,     // (B, HW) cells of 4 floats
                   const float*  __restrict__ proj,  // (128,)
                   float* __restrict__ out)          // (2, B, 128)
{
    const int t    = threadIdx.x;
    const int lane = t & 31;

    __shared__ int s_oppMin;
    __shared__ int s_foodCnt;
    __shared__ int s_minKey;

    const float pj = (t < LATENT) ? __ldg(&proj[t]) : 0.0f;

    for (int b = blockIdx.x; b < BB; b += GRID) {
        // barrier: previous row's epilogue reads of s_* are done before re-init
        __syncthreads();
        if (t == 0) { s_oppMin = INT_MAX; s_foodCnt = 0; s_minKey = INT_MAX; }

        // Zero half of the output depends on nothing: emit it up front so the
        // stores overlap the input stream instead of extending the row tail.
        if (t >= LATENT) {
            out[(size_t)BB * LATENT + (size_t)b * LATENT + (t - LATENT)] = 0.0f;
        }
        __syncthreads();

        const float4* xb = x + (size_t)b * HWC;

        // ---- Pass 1: stream the 64KB row. Register food-bitmask per thread;
        // loads batched 4-wide (MLP >= 4), evict-first (read-once).
        unsigned foodBits = 0;
        int localFood = 0;
        int localOpp  = INT_MAX;
        #pragma unroll
        for (int g = 0; g < CPT / 4; g++) {
            float4 v[4];
            #pragma unroll
            for (int j = 0; j < 4; j++)
                v[j] = __ldcs(&xb[(g * 4 + j) * NT + t]);
            #pragma unroll
            for (int j = 0; j < 4; j++) {
                const int i    = g * 4 + j;
                const int cell = i * NT + t;
                const bool food = (v[j].y == 1.0f);     // channel 1
                const bool opp  = (v[j].w == 1.0f);     // channel 3
                foodBits |= ((unsigned)food) << i;
                localFood += (int)food;
                if (opp) localOpp = min(localOpp, cell);
            }
        }
        localFood = __reduce_add_sync(0xffffffffu, localFood);
        localOpp  = __reduce_min_sync(0xffffffffu, (unsigned)localOpp);
        if (lane == 0) {
            atomicAdd(&s_foodCnt, localFood);
            atomicMin(&s_oppMin, localOpp);
        }
        __syncthreads();

        // jnp.argmax over all-false mask -> index 0
        const int oppIdx = (s_oppMin == INT_MAX) ? 0 : s_oppMin;
        const int orow = oppIdx >> 6;
        const int ocol = oppIdx & 63;

        // ---- Pass 2: argmin of integer d2 over this thread's food cells,
        // row-major tie-break. key = (d2 << 12) | cell (d2<=7938, cell<4096).
        // sqrtf in the reference is a monotone map of integer d2 with no
        // rounding collisions in range, so integer ordering is exact.
        int localKey = INT_MAX;
        unsigned fb = foodBits;
        while (fb) {
            const int i = __ffs(fb) - 1;
            fb &= fb - 1;
            const int cell = i * NT + t;
            const int dr = (cell >> 6) - orow;
            const int dc = (cell & 63) - ocol;
            const int d2 = dr * dr + dc * dc;
            localKey = min(localKey, (d2 << 12) | cell);
        }
        localKey = __reduce_min_sync(0xffffffffu, (unsigned)localKey);
        if (lane == 0) atomicMin(&s_minKey, localKey);
        __syncthreads();

        // ---- Branch logic + g write (threads 0..127 only)
        if (t < LATENT) {
            float s = 0.0f;
            const int nf = s_foodCnt;
            if (nf >= 1) {
                const bool oppAtStart = (orow == 3) && (ocol == 6);
                if (nf == 1 || !oppAtStart) {
                    const int targetRow = (s_minKey & 4095) >> 6;
                    s = (targetRow < (HH / 2)) ? 1.0f : -1.0f;
                }
            }
            out[(size_t)b * LATENT + t] = s * pj;
        }
    }
}

extern "C" void kernel_launch(void* const* d_in, const int* in_sizes, int n_in,
                              void* d_out, int out_size)
{
    const float4* x    = (const float4*)d_in[0];   // (4096,64,64,4) fp32
    const float*  proj = (const float*)d_in[1];    // (128,) fp32
    float*        out  = (float*)d_out;            // 2*4096*128 fp32

    oracle_kernel<<<GRID, NT>>>(x, proj, out);
}

// round 10
// speedup vs baseline: 1.0085x; 1.0085x over previous
#include <cuda_runtime.h>
#include <climits>

// Problem constants (fixed by reference setup_inputs)
#define BB   4096
#define HH   64
#define WW   64
#define HWC  4096          // H*W
#define LATENT 128
#define NT   256           // threads per block
#define CPT  (HWC / NT)    // 16 cells per thread
#define BATCH 8            // loads issued per dependency batch (MLP >= 8)

__global__ __launch_bounds__(NT)
void oracle_kernel(const float4* __restrict__ x,     // (B, HW) cells of 4 floats
                   const float*  __restrict__ proj,  // (128,)
                   float* __restrict__ out)          // (2, B, 128)
{
    const int b    = blockIdx.x;
    const int t    = threadIdx.x;
    const int lane = t & 31;

    __shared__ int s_oppMin;                  // min flat index of opponent
    __shared__ int s_foodCnt;
    __shared__ int s_minKey;                  // (d2 << 12) | cell

    if (t == 0) { s_oppMin = INT_MAX; s_foodCnt = 0; s_minKey = INT_MAX; }

    // Zero half of the output depends on nothing: emit it up front so these
    // stores overlap the input stream instead of extending the CTA tail.
    if (t >= LATENT) {
        out[(size_t)BB * LATENT + (size_t)b * LATENT + (t - LATENT)] = 0.0f;
    }
    __syncthreads();

    const float4* xb = x + (size_t)b * HWC;

    // ---- Pass 1: stream the 64KB row. Each thread keeps its own 16 food
    // flags in a register bitmask; loads batched 8-wide so the front of each
    // CTA puts 8 LDG.128 in flight per thread (faster per-CTA ramp).
    unsigned foodBits = 0;
    int localFood = 0;
    int localOpp  = INT_MAX;
    #pragma unroll
    for (int g = 0; g < CPT / BATCH; g++) {
        float4 v[BATCH];
        #pragma unroll
        for (int j = 0; j < BATCH; j++)
            v[j] = __ldcs(&xb[(g * BATCH + j) * NT + t]);   // read-once stream
        #pragma unroll
        for (int j = 0; j < BATCH; j++) {
            const int i    = g * BATCH + j;
            const int cell = i * NT + t;
            const bool food = (v[j].y == 1.0f);             // channel 1
            const bool opp  = (v[j].w == 1.0f);             // channel 3
            foodBits |= ((unsigned)food) << i;
            localFood += (int)food;
            if (opp) localOpp = min(localOpp, cell);
        }
    }
    // REDUX-backed warp reductions (single instruction vs 5-step shuffle tree)
    localFood = __reduce_add_sync(0xffffffffu, localFood);
    localOpp  = (int)__reduce_min_sync(0xffffffffu, (unsigned)localOpp);
    if (lane == 0) {
        atomicAdd(&s_foodCnt, localFood);
        atomicMin(&s_oppMin, localOpp);
    }
    __syncthreads();

    // jnp.argmax over all-false mask -> index 0
    const int oppIdx = (s_oppMin == INT_MAX) ? 0 : s_oppMin;
    const int orow = oppIdx >> 6;
    const int ocol = oppIdx & 63;

    // ---- Pass 2: argmin of integer d2 over this thread's food cells,
    // row-major tie-break. key = (d2 << 12) | cell  (d2 <= 7938, cell < 4096).
    // sqrtf in the reference is a monotone map of integer d2 with no rounding
    // collisions in this range, so integer ordering is exact.
    int localKey = INT_MAX;
    unsigned fb = foodBits;
    while (fb) {
        const int i = __ffs(fb) - 1;
        fb &= fb - 1;
        const int cell = i * NT + t;
        const int dr = (cell >> 6) - orow;
        const int dc = (cell & 63) - ocol;
        const int d2 = dr * dr + dc * dc;
        localKey = min(localKey, (d2 << 12) | cell);
    }
    localKey = (int)__reduce_min_sync(0xffffffffu, (unsigned)localKey);
    if (lane == 0) atomicMin(&s_minKey, localKey);
    __syncthreads();

    // ---- Branch logic + g write (threads 0..127 only)
    if (t < LATENT) {
        float s = 0.0f;
        const int nf = s_foodCnt;
        if (nf >= 1) {
            const bool oppAtStart = (orow == 3) && (ocol == 6);
            if (nf == 1 || !oppAtStart) {
                const int targetRow = (s_minKey & 4095) >> 6;
                s = (targetRow < (HH / 2)) ? 1.0f : -1.0f;
            }
        }
        out[(size_t)b * LATENT + t] = s * __ldg(&proj[t]);
    }
}

extern "C" void kernel_launch(void* const* d_in, const int* in_sizes, int n_in,
                              void* d_out, int out_size)
{
    const float4* x    = (const float4*)d_in[0];   // (4096,64,64,4) fp32
    const float*  proj = (const float*)d_in[1];    // (128,) fp32
    float*        out  = (float*)d_out;            // 2*4096*128 fp32

    oracle_kernel<<<BB, NT>>>(x, proj, out);
}